// round 2
// baseline (speedup 1.0000x reference)
#include <cuda_runtime.h>
#include <cuda_bf16.h>
#include <cstdint>

// ============================================================================
// C[8192,1024] = A[8192,4096] @ B[1024,4096]^T   (fp32 in/out)
//
// Target is base sm_103 (tcgen05 NOT available -> ptxas rejects it), so we use
// the family-portable tensor path: mma.sync.m16n8k16.bf16 with a 2-way bf16
// split of both operands (3 MMAs: hi*hi + hi*lo + lo*hi) for fp32-like
// accuracy (norm rel-err ~1.5e-5 << 1e-3).
// ============================================================================

static constexpr int M_TOTAL = 8192;
static constexpr int K_DIM   = 4096;
static constexpr int N_TOTAL = 1024;

static constexpr int BM = 128;
static constexpr int BN = 128;
static constexpr int BK = 64;          // 64 bf16 = 128 B per smem row
static constexpr int STAGES = 3;
static constexpr int NK = K_DIM / BK;  // 64

static constexpr int TILE_BYTES  = BM * BK * 2;       // 16384 per array
static constexpr int STAGE_BYTES = 4 * TILE_BYTES;    // 65536
static constexpr int SMEM_TOTAL  = STAGES * STAGE_BYTES; // 196608

// --------------------------------------------------------------------------
// Static scratch: bf16 hi/lo splits of A and B (no allocation allowed)
// --------------------------------------------------------------------------
__device__ __nv_bfloat16 g_Ahi[(size_t)M_TOTAL * K_DIM];
__device__ __nv_bfloat16 g_Alo[(size_t)M_TOTAL * K_DIM];
__device__ __nv_bfloat16 g_Bhi[(size_t)N_TOTAL * K_DIM];
__device__ __nv_bfloat16 g_Blo[(size_t)N_TOTAL * K_DIM];

// --------------------------------------------------------------------------
// Split kernel: x -> hi = bf16(x), lo = bf16(x - hi)
// --------------------------------------------------------------------------
__device__ __forceinline__ uint32_t pack_bf16x2(__nv_bfloat16 a, __nv_bfloat16 b) {
    return (uint32_t)__bfloat16_as_ushort(a) | ((uint32_t)__bfloat16_as_ushort(b) << 16);
}

__global__ void __launch_bounds__(256)
split_kernel(const float4* __restrict__ src, uint2* __restrict__ hi,
             uint2* __restrict__ lo, int n4) {
    int i = blockIdx.x * blockDim.x + threadIdx.x;
    if (i >= n4) return;
    float4 v = src[i];
    __nv_bfloat16 h0 = __float2bfloat16(v.x);
    __nv_bfloat16 h1 = __float2bfloat16(v.y);
    __nv_bfloat16 h2 = __float2bfloat16(v.z);
    __nv_bfloat16 h3 = __float2bfloat16(v.w);
    __nv_bfloat16 l0 = __float2bfloat16(v.x - __bfloat162float(h0));
    __nv_bfloat16 l1 = __float2bfloat16(v.y - __bfloat162float(h1));
    __nv_bfloat16 l2 = __float2bfloat16(v.z - __bfloat162float(h2));
    __nv_bfloat16 l3 = __float2bfloat16(v.w - __bfloat162float(h3));
    hi[i] = make_uint2(pack_bf16x2(h0, h1), pack_bf16x2(h2, h3));
    lo[i] = make_uint2(pack_bf16x2(l0, l1), pack_bf16x2(l2, l3));
}

// --------------------------------------------------------------------------
// PTX helpers (all base-target legal)
// --------------------------------------------------------------------------
__device__ __forceinline__ void cp_async16(uint32_t saddr, const void* gptr) {
    asm volatile("cp.async.cg.shared.global [%0], [%1], 16;"
                 :: "r"(saddr), "l"(__cvta_generic_to_global(gptr)) : "memory");
}

#define CP_COMMIT() asm volatile("cp.async.commit_group;" ::: "memory")
#define CP_WAIT(N)  asm volatile("cp.async.wait_group %0;" :: "n"(N) : "memory")

#define LDSM_X4(R, addr)                                                     \
    asm volatile("ldmatrix.sync.aligned.m8n8.x4.shared.b16 {%0,%1,%2,%3}, [%4];" \
                 : "=r"((R)[0]), "=r"((R)[1]), "=r"((R)[2]), "=r"((R)[3])    \
                 : "r"(addr))

#define MMA_BF16(C, A, B0, B1)                                               \
    asm volatile("mma.sync.aligned.m16n8k16.row.col.f32.bf16.bf16.f32 "      \
                 "{%0,%1,%2,%3}, {%4,%5,%6,%7}, {%8,%9}, {%0,%1,%2,%3};"     \
                 : "+f"((C)[0]), "+f"((C)[1]), "+f"((C)[2]), "+f"((C)[3])    \
                 : "r"((A)[0]), "r"((A)[1]), "r"((A)[2]), "r"((A)[3]),       \
                   "r"(B0), "r"(B1))

// smem tile layout: row-major [128 rows][64 bf16] = 128 B/row,
// 16B chunks XOR-swizzled by (row & 7) for conflict-free cp.async + ldmatrix.
__device__ __forceinline__ uint32_t swz(int row, int col_bytes) {
    return (uint32_t)(row * 128 + (col_bytes ^ ((row & 7) * 16)));
}

// --------------------------------------------------------------------------
// GEMM kernel
// --------------------------------------------------------------------------
__global__ void __launch_bounds__(256, 1)
gemm_bf16x3_kernel(float* __restrict__ C) {
    extern __shared__ uint8_t smem[];
    const uint32_t sbase = (uint32_t)__cvta_generic_to_shared(smem);

    const int tid  = threadIdx.x;
    const int lane = tid & 31;
    const int wid  = tid >> 5;
    const int wm   = (wid & 3) * 32;   // warp M offset within CTA tile
    const int wn   = (wid >> 2) * 64;  // warp N offset within CTA tile

    const int m0 = blockIdx.y * BM;
    const int n0 = blockIdx.x * BN;

    // ---- stage loader (each thread moves 4 x 16B per array) ----
    auto load_stage = [&](int s, int kt) {
        const uint32_t st = sbase + s * STAGE_BYTES;
        const int kbase = kt * BK;
        #pragma unroll
        for (int i = 0; i < 4; i++) {
            const int idx = tid + i * 256;      // 0..1023
            const int row = idx >> 3;
            const int ch  = idx & 7;
            const uint32_t soff = swz(row, ch * 16);
            const size_t ga = (size_t)(m0 + row) * K_DIM + kbase + ch * 8;
            const size_t gb = (size_t)(n0 + row) * K_DIM + kbase + ch * 8;
            cp_async16(st +                  soff, &g_Ahi[ga]);
            cp_async16(st +     TILE_BYTES + soff, &g_Alo[ga]);
            cp_async16(st + 2 * TILE_BYTES + soff, &g_Bhi[gb]);
            cp_async16(st + 3 * TILE_BYTES + soff, &g_Blo[gb]);
        }
    };

    // ---- per-thread ldmatrix address components ----
    // A frag (m16k16): lane -> row (lane&15), k-half (lane>>4)*8 elems (=16B)
    int a_row[2], a_xor[2];
    #pragma unroll
    for (int m = 0; m < 2; m++) {
        const int r = wm + m * 16 + (lane & 15);
        a_row[m] = r * 128;
        a_xor[m] = (r & 7) * 16;
    }
    const int a_colb = (lane >> 4) * 16;   // k-half byte offset
    // B frag pair (2 x n8k16): lanes map to (n 0-7,k0),(n 0-7,k8),(n 8-15,k0),(n 8-15,k8)
    int b_row[4], b_xor[4];
    #pragma unroll
    for (int p = 0; p < 4; p++) {
        const int r = wn + p * 16 + (lane & 7) + ((lane >> 4) << 3);
        b_row[p] = r * 128;
        b_xor[p] = (r & 7) * 16;
    }
    const int b_colb = ((lane >> 3) & 1) * 16;

    float acc[2][8][4];
    #pragma unroll
    for (int m = 0; m < 2; m++)
        #pragma unroll
        for (int n = 0; n < 8; n++)
            #pragma unroll
            for (int q = 0; q < 4; q++) acc[m][n][q] = 0.f;

    // ---- prologue ----
    load_stage(0, 0); CP_COMMIT();
    load_stage(1, 1); CP_COMMIT();

    // ---- mainloop ----
    for (int kt = 0; kt < NK; kt++) {
        __syncthreads();   // all warps done reading the stage about to be overwritten
        const int la = kt + STAGES - 1;
        if (la < NK) {
            load_stage(la % STAGES, la);
            CP_COMMIT();
            CP_WAIT(2);          // group kt complete
        } else if (kt == NK - 2) {
            CP_WAIT(1);
        } else {
            CP_WAIT(0);
        }
        __syncthreads();

        const uint32_t st = sbase + (kt % STAGES) * STAGE_BYTES;
        #pragma unroll
        for (int ks = 0; ks < 4; ks++) {       // four k16 steps per BK=64
            const int kb = ks * 32;            // byte offset along k
            uint32_t a[2][2][4];               // [hi/lo][mfrag]
            #pragma unroll
            for (int h = 0; h < 2; h++) {
                const uint32_t ab = st + h * TILE_BYTES;
                #pragma unroll
                for (int m = 0; m < 2; m++) {
                    const uint32_t addr = ab + a_row[m] + ((kb + a_colb) ^ a_xor[m]);
                    LDSM_X4(a[h][m], addr);
                }
            }
            uint32_t b[2][4][4];               // [hi/lo][pair] -> 2 nfrags each
            #pragma unroll
            for (int h = 0; h < 2; h++) {
                const uint32_t bb = st + (2 + h) * TILE_BYTES;
                #pragma unroll
                for (int p = 0; p < 4; p++) {
                    const uint32_t addr = bb + b_row[p] + ((kb + b_colb) ^ b_xor[p]);
                    LDSM_X4(b[h][p], addr);
                }
            }
            #pragma unroll
            for (int m = 0; m < 2; m++)
                #pragma unroll
                for (int p = 0; p < 4; p++)
                    #pragma unroll
                    for (int q = 0; q < 2; q++) {
                        float* c = acc[m][2 * p + q];
                        MMA_BF16(c, a[0][m], b[0][p][2 * q], b[0][p][2 * q + 1]); // hi*hi
                        MMA_BF16(c, a[0][m], b[1][p][2 * q], b[1][p][2 * q + 1]); // hi*lo
                        MMA_BF16(c, a[1][m], b[0][p][2 * q], b[0][p][2 * q + 1]); // lo*hi
                    }
        }
    }

    // ---- epilogue: direct STG.64 (8B-aligned float2 per quad) ----
    #pragma unroll
    for (int m = 0; m < 2; m++) {
        const int r0 = m0 + wm + m * 16 + (lane >> 2);
        #pragma unroll
        for (int n = 0; n < 8; n++) {
            const int col = n0 + wn + n * 8 + (lane & 3) * 2;
            float2* p0 = reinterpret_cast<float2*>(&C[(size_t)r0 * N_TOTAL + col]);
            float2* p1 = reinterpret_cast<float2*>(&C[(size_t)(r0 + 8) * N_TOTAL + col]);
            *p0 = make_float2(acc[m][n][0], acc[m][n][1]);
            *p1 = make_float2(acc[m][n][2], acc[m][n][3]);
        }
    }
}

// --------------------------------------------------------------------------
// Launch
// --------------------------------------------------------------------------
extern "C" void kernel_launch(void* const* d_in, const int* in_sizes, int n_in,
                              void* d_out, int out_size) {
    const float* A = (const float*)d_in[0];   // [8192, 4096] (A_locals flattened)
    const float* B = (const float*)d_in[1];   // [1024, 4096]
    float* C = (float*)d_out;                 // [8192, 1024]

    __nv_bfloat16 *aHi, *aLo, *bHi, *bLo;
    cudaGetSymbolAddress((void**)&aHi, g_Ahi);
    cudaGetSymbolAddress((void**)&aLo, g_Alo);
    cudaGetSymbolAddress((void**)&bHi, g_Bhi);
    cudaGetSymbolAddress((void**)&bLo, g_Blo);

    const int nA4 = (M_TOTAL * K_DIM) / 4;    // 8388608
    const int nB4 = (N_TOTAL * K_DIM) / 4;    // 1048576
    split_kernel<<<(nA4 + 255) / 256, 256>>>((const float4*)A, (uint2*)aHi, (uint2*)aLo, nA4);
    split_kernel<<<(nB4 + 255) / 256, 256>>>((const float4*)B, (uint2*)bHi, (uint2*)bLo, nB4);

    static bool attr_set = false;
    if (!attr_set) {
        cudaFuncSetAttribute(gemm_bf16x3_kernel,
                             cudaFuncAttributeMaxDynamicSharedMemorySize, SMEM_TOTAL);
        attr_set = true;
    }
    dim3 grid(N_TOTAL / BN, M_TOTAL / BM);    // (8, 64)
    gemm_bf16x3_kernel<<<grid, 256, SMEM_TOTAL>>>(C);
}

// round 3
// speedup vs baseline: 2.4649x; 2.4649x over previous
#include <cuda_runtime.h>
#include <cuda_fp16.h>
#include <cstdint>

// ============================================================================
// C[8192,1024] = A[8192,4096] @ B[1024,4096]^T   (fp32 in/out)
//
// Base sm_103 target (no tcgen05). Single-pass fp16 mma.sync.m16n8k16:
// fp16 rounding gives norm rel-err ~4e-4 << 1e-3 gate (error model validated
// in R2: predicted ~1e-5 for 3-MMA bf16, measured 1.47e-5).
// ============================================================================

static constexpr int M_TOTAL = 8192;
static constexpr int K_DIM   = 4096;
static constexpr int N_TOTAL = 1024;

static constexpr int BM = 128;
static constexpr int BN = 128;
static constexpr int BK = 64;          // 64 fp16 = 128 B per smem row
static constexpr int STAGES = 3;
static constexpr int NK = K_DIM / BK;  // 64

static constexpr int TILE_BYTES  = BM * BK * 2;       // 16384 per array
static constexpr int STAGE_BYTES = 2 * TILE_BYTES;    // 32768 (A + B)
static constexpr int SMEM_TOTAL  = STAGES * STAGE_BYTES; // 98304 -> 2 CTAs/SM

// --------------------------------------------------------------------------
// Static scratch: fp16 copies of A and B
// --------------------------------------------------------------------------
__device__ __half g_Ah[(size_t)M_TOTAL * K_DIM];
__device__ __half g_Bh[(size_t)N_TOTAL * K_DIM];

// --------------------------------------------------------------------------
// Convert kernel: fp32 -> fp16 (vectorized 4-wide)
// --------------------------------------------------------------------------
__global__ void __launch_bounds__(256)
cvt_kernel(const float4* __restrict__ src, uint2* __restrict__ dst, int n4) {
    int i = blockIdx.x * blockDim.x + threadIdx.x;
    if (i >= n4) return;
    float4 v = src[i];
    __half2 lo = __floats2half2_rn(v.x, v.y);
    __half2 hi = __floats2half2_rn(v.z, v.w);
    dst[i] = make_uint2(*reinterpret_cast<uint32_t*>(&lo), *reinterpret_cast<uint32_t*>(&hi));
}

// --------------------------------------------------------------------------
// PTX helpers (base-target legal)
// --------------------------------------------------------------------------
__device__ __forceinline__ void cp_async16(uint32_t saddr, const void* gptr) {
    asm volatile("cp.async.cg.shared.global [%0], [%1], 16;"
                 :: "r"(saddr), "l"(__cvta_generic_to_global(gptr)) : "memory");
}

#define CP_COMMIT() asm volatile("cp.async.commit_group;" ::: "memory")
#define CP_WAIT(N)  asm volatile("cp.async.wait_group %0;" :: "n"(N) : "memory")

#define LDSM_X4(R, addr)                                                     \
    asm volatile("ldmatrix.sync.aligned.m8n8.x4.shared.b16 {%0,%1,%2,%3}, [%4];" \
                 : "=r"((R)[0]), "=r"((R)[1]), "=r"((R)[2]), "=r"((R)[3])    \
                 : "r"(addr))

#define MMA_F16(C, A, B0, B1)                                                \
    asm volatile("mma.sync.aligned.m16n8k16.row.col.f32.f16.f16.f32 "        \
                 "{%0,%1,%2,%3}, {%4,%5,%6,%7}, {%8,%9}, {%0,%1,%2,%3};"     \
                 : "+f"((C)[0]), "+f"((C)[1]), "+f"((C)[2]), "+f"((C)[3])    \
                 : "r"((A)[0]), "r"((A)[1]), "r"((A)[2]), "r"((A)[3]),       \
                   "r"(B0), "r"(B1))

// smem tile layout: row-major [128 rows][64 fp16] = 128 B/row,
// 16B chunks XOR-swizzled by (row & 7): conflict-free cp.async + ldmatrix.
__device__ __forceinline__ uint32_t swz(int row, int col_bytes) {
    return (uint32_t)(row * 128 + (col_bytes ^ ((row & 7) * 16)));
}

// --------------------------------------------------------------------------
// GEMM kernel: CTA 128x128x64, warp 32x64, 3-stage cp.async, 2 CTAs/SM
// --------------------------------------------------------------------------
__global__ void __launch_bounds__(256, 2)
gemm_f16_kernel(float* __restrict__ C) {
    extern __shared__ uint8_t smem[];
    const uint32_t sbase = (uint32_t)__cvta_generic_to_shared(smem);

    const int tid  = threadIdx.x;
    const int lane = tid & 31;
    const int wid  = tid >> 5;
    const int wm   = (wid & 3) * 32;   // warp M offset
    const int wn   = (wid >> 2) * 64;  // warp N offset

    const int m0 = blockIdx.y * BM;
    const int n0 = blockIdx.x * BN;

    // ---- stage loader: 1024 x 16B chunks per array, 256 threads x 4 ----
    auto load_stage = [&](int s, int kt) {
        const uint32_t st = sbase + s * STAGE_BYTES;
        const int kbase = kt * BK;
        #pragma unroll
        for (int i = 0; i < 4; i++) {
            const int idx = tid + i * 256;
            const int row = idx >> 3;
            const int ch  = idx & 7;
            const uint32_t soff = swz(row, ch * 16);
            cp_async16(st +              soff, &g_Ah[(size_t)(m0 + row) * K_DIM + kbase + ch * 8]);
            cp_async16(st + TILE_BYTES + soff, &g_Bh[(size_t)(n0 + row) * K_DIM + kbase + ch * 8]);
        }
    };

    // ---- ldmatrix address components (validated in R2) ----
    int a_row[2], a_xor[2];
    #pragma unroll
    for (int m = 0; m < 2; m++) {
        const int r = wm + m * 16 + (lane & 15);
        a_row[m] = r * 128;
        a_xor[m] = (r & 7) * 16;
    }
    const int a_colb = (lane >> 4) * 16;
    int b_row[4], b_xor[4];
    #pragma unroll
    for (int p = 0; p < 4; p++) {
        const int r = wn + p * 16 + (lane & 7) + ((lane >> 4) << 3);
        b_row[p] = r * 128;
        b_xor[p] = (r & 7) * 16;
    }
    const int b_colb = ((lane >> 3) & 1) * 16;

    float acc[2][8][4];
    #pragma unroll
    for (int m = 0; m < 2; m++)
        #pragma unroll
        for (int n = 0; n < 8; n++)
            #pragma unroll
            for (int q = 0; q < 4; q++) acc[m][n][q] = 0.f;

    // ---- prologue: 2 stages in flight ----
    load_stage(0, 0); CP_COMMIT();
    load_stage(1, 1); CP_COMMIT();

    // ---- mainloop: ONE barrier per k-iter ----
    for (int kt = 0; kt < NK; kt++) {
        if (kt < NK - 1) { CP_WAIT(1); } else { CP_WAIT(0); }
        __syncthreads();   // stage kt ready AND everyone done with stage kt-1
        if (kt + 2 < NK) {
            load_stage((kt + 2) % STAGES, kt + 2);   // overwrites stage kt-1
            CP_COMMIT();
        }

        const uint32_t st = sbase + (kt % STAGES) * STAGE_BYTES;
        #pragma unroll
        for (int ks = 0; ks < 4; ks++) {        // four k16 steps in BK=64
            const int kb = ks * 32;             // k byte offset
            uint32_t a[2][4];
            #pragma unroll
            for (int m = 0; m < 2; m++)
                LDSM_X4(a[m], st + a_row[m] + ((kb + a_colb) ^ a_xor[m]));
            uint32_t b[4][4];
            #pragma unroll
            for (int p = 0; p < 4; p++)
                LDSM_X4(b[p], st + TILE_BYTES + b_row[p] + ((kb + b_colb) ^ b_xor[p]));
            #pragma unroll
            for (int m = 0; m < 2; m++)
                #pragma unroll
                for (int p = 0; p < 4; p++)
                    #pragma unroll
                    for (int q = 0; q < 2; q++)
                        MMA_F16(acc[m][2 * p + q], a[m], b[p][2 * q], b[p][2 * q + 1]);
        }
    }

    // ---- epilogue: direct STG.64 ----
    #pragma unroll
    for (int m = 0; m < 2; m++) {
        const int r0 = m0 + wm + m * 16 + (lane >> 2);
        #pragma unroll
        for (int n = 0; n < 8; n++) {
            const int col = n0 + wn + n * 8 + (lane & 3) * 2;
            float2* p0 = reinterpret_cast<float2*>(&C[(size_t)r0 * N_TOTAL + col]);
            float2* p1 = reinterpret_cast<float2*>(&C[(size_t)(r0 + 8) * N_TOTAL + col]);
            *p0 = make_float2(acc[m][n][0], acc[m][n][1]);
            *p1 = make_float2(acc[m][n][2], acc[m][n][3]);
        }
    }
}

// --------------------------------------------------------------------------
// Launch
// --------------------------------------------------------------------------
extern "C" void kernel_launch(void* const* d_in, const int* in_sizes, int n_in,
                              void* d_out, int out_size) {
    const float* A = (const float*)d_in[0];   // [8192, 4096]
    const float* B = (const float*)d_in[1];   // [1024, 4096]
    float* C = (float*)d_out;                 // [8192, 1024]

    __half *aH, *bH;
    cudaGetSymbolAddress((void**)&aH, g_Ah);
    cudaGetSymbolAddress((void**)&bH, g_Bh);

    const int nA4 = (M_TOTAL * K_DIM) / 4;
    const int nB4 = (N_TOTAL * K_DIM) / 4;
    cvt_kernel<<<(nA4 + 255) / 256, 256>>>((const float4*)A, (uint2*)aH, nA4);
    cvt_kernel<<<(nB4 + 255) / 256, 256>>>((const float4*)B, (uint2*)bH, nB4);

    static bool attr_set = false;
    if (!attr_set) {
        cudaFuncSetAttribute(gemm_f16_kernel,
                             cudaFuncAttributeMaxDynamicSharedMemorySize, SMEM_TOTAL);
        attr_set = true;
    }
    dim3 grid(N_TOTAL / BN, M_TOTAL / BM);    // (8, 64): n-fastest -> A tile L2 reuse
    gemm_f16_kernel<<<grid, 256, SMEM_TOTAL>>>(C);
}